// round 1
// baseline (speedup 1.0000x reference)
#include <cuda_runtime.h>

// ---------------- problem constants ----------------
#define NN 15000          // nodes
#define NE 60000          // edges
#define ND 64             // NODE_DIM
#define HD 64             // HID
#define ED 33             // EDGE_DIM
#define CT 4160           // 65*64: T columns (j=0..63 from w2, j=64 = b2 row)

// ---------------- device scratch (static globals: allocation-free) ----------------
__device__ float g_xf[NN * ND];          // node features           3.84 MB
__device__ float g_h[NE * HD];           // edge MLP hidden        15.36 MB
__device__ float g_M[ND * CT];           // permuted mlp_w2 (+b2)   1.06 MB
__device__ float g_T[(size_t)NN * CT];   // per-node tensor        249.6 MB
__device__ float g_sums[NN * HD];        // scatter accumulator     3.84 MB
__device__ float g_cnt[NN];              // in-degree (float)

// ---------------- K1: node features + zero accumulators (1 warp / node) ----------------
__global__ void k_node_prep(const float* __restrict__ x,
                            const int* __restrict__ inp,
                            const int* __restrict__ outp,
                            const float* __restrict__ in_emb,
                            const float* __restrict__ out_emb) {
    int gw = (blockIdx.x * blockDim.x + threadIdx.x) >> 5;
    int l = threadIdx.x & 31;
    if (gw >= NN) return;
    int n = gw;
    float v0 = x[n * 32 + l];                                   // cols 0..31
    float v1 = (l < 16) ? in_emb[inp[n] * 16 + l]               // cols 32..47
                        : out_emb[outp[n] * 16 + (l - 16)];     // cols 48..63
    g_xf[n * 64 + l] = v0;
    g_xf[n * 64 + 32 + l] = v1;
    g_sums[n * 64 + l] = 0.f;
    g_sums[n * 64 + 32 + l] = 0.f;
    if (l == 0) g_cnt[n] = 0.f;
}

// ---------------- K2: permute mlp_w2 into M[i, j*64+o] = w2[j, i*64+o]; row j=64 = b2 ----------------
__global__ void k_build_M(const float* __restrict__ w2, const float* __restrict__ b2) {
    int idx = blockIdx.x * blockDim.x + threadIdx.x;
    if (idx >= ND * CT) return;
    int i = idx / CT;
    int col = idx - i * CT;
    int j = col >> 6;
    int o = col & 63;
    g_M[idx] = (j < 64) ? w2[j * 4096 + i * 64 + o] : b2[i * 64 + o];
}

// ---------------- K3: edge MLP h = relu(ea @ w1 + b1) (1 warp / edge) ----------------
__global__ void k_edge_mlp(const int* __restrict__ e_nt, const int* __restrict__ e_np,
                           const float* __restrict__ e_sc,
                           const float* __restrict__ nt_emb, const float* __restrict__ np_emb,
                           const float* __restrict__ w1, const float* __restrict__ b1) {
    __shared__ float w1s[ED * 64];
    __shared__ float b1s[64];
    __shared__ float eas[8][34];
    int tid = threadIdx.x;
    for (int i = tid; i < ED * 64; i += 256) w1s[i] = w1[i];
    if (tid < 64) b1s[tid] = b1[tid];
    __syncthreads();
    int w = tid >> 5, l = tid & 31;
    int e = blockIdx.x * 8 + w;
    if (e >= NE) return;
    if (l < 16) eas[w][l] = nt_emb[e_nt[e] * 16 + l];
    else        eas[w][l] = np_emb[e_np[e] * 16 + (l - 16)];
    if (l == 0) eas[w][32] = e_sc[e];
    __syncwarp();
    int o0 = l, o1 = l + 32;
    float a0 = b1s[o0], a1 = b1s[o1];
#pragma unroll
    for (int k = 0; k < ED; k++) {
        float v = eas[w][k];
        a0 = fmaf(v, w1s[k * 64 + o0], a0);
        a1 = fmaf(v, w1s[k * 64 + o1], a1);
    }
    g_h[e * 64 + o0] = fmaxf(a0, 0.f);
    g_h[e * 64 + o1] = fmaxf(a1, 0.f);
}

// ---------------- K4: GEMM  T[NN, CT] = g_xf[NN,64] @ g_M[64, CT] ----------------
// Tile: 128 rows x 64 cols, K=64, 256 threads, 8x4 per-thread register tile.
__global__ void k_gemm() {
    extern __shared__ float sm[];
    float* As = sm;                // [128][68] row-major with pad (A tile, natural layout)
    float* Bs = sm + 128 * 68;     // [64][64]
    int tid = threadIdx.x;
    int c0 = blockIdx.x * 64;
    int r0 = blockIdx.y * 128;

    for (int idx = tid; idx < 128 * 64; idx += 256) {
        int r = idx >> 6, k = idx & 63;
        int row = r0 + r;
        As[r * 68 + k] = (row < NN) ? g_xf[row * 64 + k] : 0.f;
    }
    for (int idx = tid; idx < 64 * 64; idx += 256) {
        int k = idx >> 6, o = idx & 63;
        Bs[k * 64 + o] = g_M[k * CT + c0 + o];
    }
    __syncthreads();

    int tx = tid & 15, ty = tid >> 4;
    int m0 = ty * 8, n0 = tx * 4;
    float acc[8][4];
#pragma unroll
    for (int i = 0; i < 8; i++)
#pragma unroll
        for (int j = 0; j < 4; j++) acc[i][j] = 0.f;

#pragma unroll 8
    for (int k = 0; k < 64; k++) {
        float4 b4 = *(const float4*)&Bs[k * 64 + n0];
#pragma unroll
        for (int i = 0; i < 8; i++) {
            float a = As[(m0 + i) * 68 + k];
            acc[i][0] = fmaf(a, b4.x, acc[i][0]);
            acc[i][1] = fmaf(a, b4.y, acc[i][1]);
            acc[i][2] = fmaf(a, b4.z, acc[i][2]);
            acc[i][3] = fmaf(a, b4.w, acc[i][3]);
        }
    }
#pragma unroll
    for (int i = 0; i < 8; i++) {
        int row = r0 + m0 + i;
        if (row < NN) {
            float4 v = make_float4(acc[i][0], acc[i][1], acc[i][2], acc[i][3]);
            *(float4*)&g_T[(size_t)row * CT + c0 + n0] = v;
        }
    }
}

// ---------------- K5: per-edge message + scatter-add (1 warp / edge) ----------------
// msg[e,o] = sum_{j<64} h[e,j]*T[src, j*64+o] + T[src, 64*64+o]   (b2 row)
__global__ void k_edge_gather(const int* __restrict__ eidx) {
    __shared__ float hs[8][64];
    int tid = threadIdx.x, w = tid >> 5, l = tid & 31;
    int e = blockIdx.x * 8 + w;
    if (e >= NE) return;
    int src = eidx[e];
    int dst = eidx[NE + e];
    hs[w][l] = g_h[e * 64 + l];
    hs[w][l + 32] = g_h[e * 64 + 32 + l];
    __syncwarp();
    const float* Tr = g_T + (size_t)src * CT;
    float a0 = Tr[4096 + l];        // h'[64] = 1 -> b2 contribution
    float a1 = Tr[4096 + 32 + l];
#pragma unroll 8
    for (int j = 0; j < 64; j++) {
        float v = hs[w][j];
        a0 = fmaf(v, Tr[j * 64 + l], a0);
        a1 = fmaf(v, Tr[j * 64 + 32 + l], a1);
    }
    atomicAdd(&g_sums[dst * 64 + l], a0);
    atomicAdd(&g_sums[dst * 64 + 32 + l], a1);
    if (l == 0) atomicAdd(&g_cnt[dst], 1.f);
}

// ---------------- K6: scatter-mean + root + ReLU + 4 heads (1 warp / node) ----------------
// dynamic smem layout: rw[4096] | cb[64] | Wc[64*240] | bc[240] | stage[8*128]
__global__ void k_final(const float* __restrict__ root_w, const float* __restrict__ conv_b,
                        const float* __restrict__ wsu, const float* __restrict__ bsu,
                        const float* __restrict__ wnt, const float* __restrict__ bnt,
                        const float* __restrict__ wtg, const float* __restrict__ btg,
                        const float* __restrict__ wpr, const float* __restrict__ bpr,
                        float* __restrict__ out) {
    extern __shared__ float sm[];
    float* rw = sm;                  // 4096
    float* cb = rw + 4096;           // 64
    float* Wc = cb + 64;             // 64*240
    float* bc = Wc + 64 * 240;       // 240
    float* stage = bc + 240;         // 8 * 128
    int tid = threadIdx.x;
    for (int i = tid; i < 4096; i += 256) rw[i] = root_w[i];
    if (tid < 64) cb[tid] = conv_b[tid];
    for (int i = tid; i < 64 * 16; i += 256)  { int r = i >> 4, c = i & 15;  Wc[r * 240 + c]       = wsu[i]; }
    for (int i = tid; i < 64 * 32; i += 256)  { int r = i >> 5, c = i & 31;  Wc[r * 240 + 16 + c]  = wnt[i]; }
    for (int i = tid; i < 64 * 64; i += 256)  { int r = i >> 6, c = i & 63;  Wc[r * 240 + 48 + c]  = wtg[i]; }
    for (int i = tid; i < 64 * 128; i += 256) { int r = i >> 7, c = i & 127; Wc[r * 240 + 112 + c] = wpr[i]; }
    if (tid < 16)       bc[tid] = bsu[tid];
    else if (tid < 48)  bc[tid] = bnt[tid - 16];
    else if (tid < 112) bc[tid] = btg[tid - 48];
    else if (tid < 240) bc[tid] = bpr[tid - 112];
    __syncthreads();

    int w = tid >> 5, l = tid & 31;
    int n = blockIdx.x * 8 + w;
    if (n >= NN) return;
    float* xs = stage + w * 128;
    float* os = xs + 64;
    xs[l] = g_xf[n * 64 + l];
    xs[l + 32] = g_xf[n * 64 + 32 + l];
    __syncwarp();

    float inv = 1.f / fmaxf(g_cnt[n], 1.f);
#pragma unroll
    for (int half = 0; half < 2; half++) {
        int o = l + 32 * half;
        float acc = cb[o] + g_sums[n * 64 + o] * inv;
#pragma unroll 8
        for (int i = 0; i < 64; i++) acc = fmaf(xs[i], rw[i * 64 + o], acc);
        os[o] = fmaxf(acc, 0.f);
    }
    __syncwarp();

#pragma unroll
    for (int q = 0; q < 8; q++) {
        int t = l + 32 * q;
        if (t < 240) {
            float acc = bc[t];
#pragma unroll 8
            for (int i = 0; i < 64; i++) acc = fmaf(os[i], Wc[i * 240 + t], acc);
            if (t < 16)       out[n * 16 + t] = acc;
            else if (t < 48)  out[240000  + n * 32  + (t - 16)]  = acc;
            else if (t < 112) out[720000  + n * 64  + (t - 48)]  = acc;
            else              out[1680000 + n * 128 + (t - 112)] = acc;
        }
    }
}

// ---------------- launch ----------------
extern "C" void kernel_launch(void* const* d_in, const int* in_sizes, int n_in,
                              void* d_out, int out_size) {
    const float* x        = (const float*)d_in[0];
    const int*   input_np = (const int*)  d_in[1];
    const int*   output_np= (const int*)  d_in[2];
    const int*   edge_idx = (const int*)  d_in[3];
    const int*   edge_nt  = (const int*)  d_in[4];
    const int*   edge_np  = (const int*)  d_in[5];
    const float* edge_sc  = (const float*)d_in[6];
    const float* in_emb   = (const float*)d_in[7];
    const float* out_emb  = (const float*)d_in[8];
    const float* enp_emb  = (const float*)d_in[9];
    const float* ent_emb  = (const float*)d_in[10];
    const float* w1       = (const float*)d_in[11];
    const float* b1       = (const float*)d_in[12];
    const float* w2       = (const float*)d_in[13];
    const float* b2       = (const float*)d_in[14];
    const float* root_w   = (const float*)d_in[15];
    const float* conv_b   = (const float*)d_in[16];
    const float* wsu      = (const float*)d_in[17];
    const float* bsu      = (const float*)d_in[18];
    const float* wnt      = (const float*)d_in[19];
    const float* bnt      = (const float*)d_in[20];
    const float* wtg      = (const float*)d_in[21];
    const float* btg      = (const float*)d_in[22];
    const float* wpr      = (const float*)d_in[23];
    const float* bpr      = (const float*)d_in[24];
    float* out = (float*)d_out;

    const int smem_gemm  = (128 * 68 + 64 * 64) * 4;                       // 51200 B
    const int smem_final = (4096 + 64 + 64 * 240 + 240 + 8 * 128) * 4;     // 83136 B
    cudaFuncSetAttribute(k_gemm,  cudaFuncAttributeMaxDynamicSharedMemorySize, smem_gemm);
    cudaFuncSetAttribute(k_final, cudaFuncAttributeMaxDynamicSharedMemorySize, smem_final);

    k_node_prep<<<(NN + 7) / 8, 256>>>(x, input_np, output_np, in_emb, out_emb);
    k_build_M<<<(ND * CT + 255) / 256, 256>>>(w2, b2);
    k_edge_mlp<<<(NE + 7) / 8, 256>>>(edge_nt, edge_np, edge_sc, ent_emb, enp_emb, w1, b1);
    dim3 ggrid(CT / 64, (NN + 127) / 128);
    k_gemm<<<ggrid, 256, smem_gemm>>>();
    k_edge_gather<<<(NE + 7) / 8, 256>>>(edge_idx);
    k_final<<<(NN + 7) / 8, 256, smem_final>>>(root_w, conv_b,
                                               wsu, bsu, wnt, bnt, wtg, btg, wpr, bpr, out);
}

// round 2
// speedup vs baseline: 1.0513x; 1.0513x over previous
#include <cuda_runtime.h>

// ---------------- problem constants ----------------
#define NN 15000          // nodes
#define NE 60000          // edges
#define ND 64             // NODE_DIM
#define HD 64             // HID
#define ED 33             // EDGE_DIM
#define CT 4160           // 65*64: T columns (j=0..63 from w2, j=64 = b2 row)

// ---------------- device scratch (static globals: allocation-free) ----------------
__device__ float g_xf[NN * ND];          // node features           3.84 MB
__device__ float g_h[NE * HD];           // edge MLP hidden        15.36 MB
__device__ float g_M[ND * CT];           // permuted mlp_w2 (+b2)   1.06 MB
__device__ float g_T[(size_t)NN * CT];   // per-node tensor        249.6 MB
__device__ float g_sums[NN * HD];        // scatter accumulator     3.84 MB
__device__ float g_cnt[NN];              // in-degree (float)
// CSR (edges grouped by src)
__device__ int g_hist[NN];
__device__ int g_off[NN + 1];
__device__ int g_cursor[NN];
__device__ int g_sorted[NE];

// ---------------- K1: node features + zero accumulators (1 warp / node) ----------------
__global__ void k_node_prep(const float* __restrict__ x,
                            const int* __restrict__ inp,
                            const int* __restrict__ outp,
                            const float* __restrict__ in_emb,
                            const float* __restrict__ out_emb) {
    int gw = (blockIdx.x * blockDim.x + threadIdx.x) >> 5;
    int l = threadIdx.x & 31;
    if (gw >= NN) return;
    int n = gw;
    float v0 = x[n * 32 + l];                                   // cols 0..31
    float v1 = (l < 16) ? in_emb[inp[n] * 16 + l]               // cols 32..47
                        : out_emb[outp[n] * 16 + (l - 16)];     // cols 48..63
    g_xf[n * 64 + l] = v0;
    g_xf[n * 64 + 32 + l] = v1;
    g_sums[n * 64 + l] = 0.f;
    g_sums[n * 64 + 32 + l] = 0.f;
    if (l == 0) { g_cnt[n] = 0.f; g_hist[n] = 0; }
}

// ---------------- CSR build: histogram of src ----------------
__global__ void k_hist(const int* __restrict__ eidx) {
    int e = blockIdx.x * blockDim.x + threadIdx.x;
    if (e >= NE) return;
    atomicAdd(&g_hist[eidx[e]], 1);
}

// ---------------- CSR build: exclusive scan (single block, 1024 threads) ----------------
__global__ void k_scan() {
    __shared__ int warp_sums[32];
    __shared__ int s_carry;
    int tid = threadIdx.x;
    int lane = tid & 31, wid = tid >> 5;
    if (tid == 0) { s_carry = 0; g_off[0] = 0; }
    __syncthreads();
    for (int base = 0; base < NN; base += 1024) {
        int i = base + tid;
        int v = (i < NN) ? g_hist[i] : 0;
        int xv = v;
#pragma unroll
        for (int d = 1; d < 32; d <<= 1) {
            int y = __shfl_up_sync(0xffffffffu, xv, d);
            if (lane >= d) xv += y;
        }
        if (lane == 31) warp_sums[wid] = xv;
        __syncthreads();
        if (tid < 32) {
            int w = warp_sums[tid];
#pragma unroll
            for (int d = 1; d < 32; d <<= 1) {
                int y = __shfl_up_sync(0xffffffffu, w, d);
                if (tid >= d) w += y;
            }
            warp_sums[tid] = w;
        }
        __syncthreads();
        int incl = xv + ((wid > 0) ? warp_sums[wid - 1] : 0) + s_carry;
        if (i < NN) { g_off[i + 1] = incl; g_cursor[i] = incl - v; }
        __syncthreads();
        if (tid == 0) s_carry += warp_sums[31];
        __syncthreads();
    }
}

// ---------------- CSR build: scatter edge ids ----------------
__global__ void k_scatter(const int* __restrict__ eidx) {
    int e = blockIdx.x * blockDim.x + threadIdx.x;
    if (e >= NE) return;
    int pos = atomicAdd(&g_cursor[eidx[e]], 1);
    g_sorted[pos] = e;
}

// ---------------- K2: permute mlp_w2 into M[i, j*64+o] = w2[j, i*64+o]; row j=64 = b2 ----------------
__global__ void k_build_M(const float* __restrict__ w2, const float* __restrict__ b2) {
    int idx = blockIdx.x * blockDim.x + threadIdx.x;
    if (idx >= ND * CT) return;
    int i = idx / CT;
    int col = idx - i * CT;
    int j = col >> 6;
    int o = col & 63;
    g_M[idx] = (j < 64) ? w2[j * 4096 + i * 64 + o] : b2[i * 64 + o];
}

// ---------------- K3: edge MLP h = relu(ea @ w1 + b1) (1 warp / edge) ----------------
__global__ void k_edge_mlp(const int* __restrict__ e_nt, const int* __restrict__ e_np,
                           const float* __restrict__ e_sc,
                           const float* __restrict__ nt_emb, const float* __restrict__ np_emb,
                           const float* __restrict__ w1, const float* __restrict__ b1) {
    __shared__ float w1s[ED * 64];
    __shared__ float b1s[64];
    __shared__ float eas[8][34];
    int tid = threadIdx.x;
    for (int i = tid; i < ED * 64; i += 256) w1s[i] = w1[i];
    if (tid < 64) b1s[tid] = b1[tid];
    __syncthreads();
    int w = tid >> 5, l = tid & 31;
    int e = blockIdx.x * 8 + w;
    if (e >= NE) return;
    if (l < 16) eas[w][l] = nt_emb[e_nt[e] * 16 + l];
    else        eas[w][l] = np_emb[e_np[e] * 16 + (l - 16)];
    if (l == 0) eas[w][32] = e_sc[e];
    __syncwarp();
    int o0 = l, o1 = l + 32;
    float a0 = b1s[o0], a1 = b1s[o1];
#pragma unroll
    for (int k = 0; k < ED; k++) {
        float v = eas[w][k];
        a0 = fmaf(v, w1s[k * 64 + o0], a0);
        a1 = fmaf(v, w1s[k * 64 + o1], a1);
    }
    g_h[e * 64 + o0] = fmaxf(a0, 0.f);
    g_h[e * 64 + o1] = fmaxf(a1, 0.f);
}

// ---------------- K4: GEMM  T[NN, CT] = g_xf[NN,64] @ g_M[64, CT] ----------------
// Tile 128m x 64n, K=64, 128 threads, 8x8 register tile, A transposed in smem.
__global__ __launch_bounds__(128, 4) void k_gemm() {
    extern __shared__ float sm[];
    float* At = sm;              // [64][132]  (k-major, padded)
    float* Bs = sm + 64 * 132;   // [64][64]
    int tid = threadIdx.x;
    int c0 = blockIdx.x * 64;
    int r0 = blockIdx.y * 128;

    // A load: thread tid owns row r0+tid, transposes into At[k][m]
    {
        int row = r0 + tid;
        if (row < NN) {
            const float4* ap = (const float4*)(g_xf + row * 64);
#pragma unroll
            for (int q = 0; q < 16; q++) {
                float4 v = ap[q];
                At[(4 * q + 0) * 132 + tid] = v.x;
                At[(4 * q + 1) * 132 + tid] = v.y;
                At[(4 * q + 2) * 132 + tid] = v.z;
                At[(4 * q + 3) * 132 + tid] = v.w;
            }
        } else {
#pragma unroll
            for (int k = 0; k < 64; k++) At[k * 132 + tid] = 0.f;
        }
    }
    // B load: 64 rows x 64 cols from g_M (row stride CT)
    {
#pragma unroll
        for (int q = 0; q < 8; q++) {
            int idx = q * 128 + tid;           // float4 index, 1024 total
            int k = idx >> 4;
            int c = idx & 15;
            ((float4*)Bs)[k * 16 + c] = *(const float4*)&g_M[k * CT + c0 + c * 4];
        }
    }
    __syncthreads();

    int m0 = (tid >> 3) * 8;   // 16 m-groups
    int n0 = (tid & 7) * 8;    // 8 n-groups
    float acc[8][8];
#pragma unroll
    for (int i = 0; i < 8; i++)
#pragma unroll
        for (int j = 0; j < 8; j++) acc[i][j] = 0.f;

#pragma unroll 4
    for (int k = 0; k < 64; k++) {
        float4 a0 = *(const float4*)&At[k * 132 + m0];
        float4 a1 = *(const float4*)&At[k * 132 + m0 + 4];
        float4 b0 = *(const float4*)&Bs[k * 64 + n0];
        float4 b1 = *(const float4*)&Bs[k * 64 + n0 + 4];
        float am[8] = {a0.x, a0.y, a0.z, a0.w, a1.x, a1.y, a1.z, a1.w};
        float bn[8] = {b0.x, b0.y, b0.z, b0.w, b1.x, b1.y, b1.z, b1.w};
#pragma unroll
        for (int i = 0; i < 8; i++)
#pragma unroll
            for (int j = 0; j < 8; j++)
                acc[i][j] = fmaf(am[i], bn[j], acc[i][j]);
    }
#pragma unroll
    for (int i = 0; i < 8; i++) {
        int row = r0 + m0 + i;
        if (row < NN) {
            float* dp = g_T + (size_t)row * CT + c0 + n0;
            *(float4*)dp       = make_float4(acc[i][0], acc[i][1], acc[i][2], acc[i][3]);
            *(float4*)(dp + 4) = make_float4(acc[i][4], acc[i][5], acc[i][6], acc[i][7]);
        }
    }
}

// ---------------- K5: per-src-node edge apply (1 block / node, T row in smem) ----------------
// msg[e,o] = sum_{j<64} h[e,j]*ts[j*64+o] + ts[4096+o]; scatter-add to g_sums[dst]
__global__ void k_edge_apply(const int* __restrict__ eidx) {
    __shared__ float ts[CT];
    __shared__ float hs[2][64];
    int n = blockIdx.x;
    int beg = g_off[n], end = g_off[n + 1];
    if (beg == end) return;
    int tid = threadIdx.x;                    // 128 threads
    const float4* Tp = (const float4*)(g_T + (size_t)n * CT);
    float4* tsp = (float4*)ts;
    for (int i = tid; i < CT / 4; i += 128) tsp[i] = Tp[i];
    __syncthreads();

    int half = tid >> 6;                       // which edge of the pair
    int o = tid & 63;
    for (int p = beg; p < end; p += 2) {
        int idx = p + half;
        int e = -1;
        if (idx < end) {
            e = g_sorted[idx];
            hs[half][o] = g_h[e * 64 + o];
        }
        __syncthreads();
        if (e >= 0) {
            int dst = eidx[NE + e];
            float acc = ts[4096 + o];
#pragma unroll 16
            for (int j = 0; j < 64; j++) acc = fmaf(hs[half][j], ts[j * 64 + o], acc);
            atomicAdd(&g_sums[dst * 64 + o], acc);
            if (o == 0) atomicAdd(&g_cnt[dst], 1.f);
        }
        __syncthreads();
    }
}

// ---------------- K6: scatter-mean + root + ReLU + 4 heads (1 warp / node) ----------------
__global__ void k_final(const float* __restrict__ root_w, const float* __restrict__ conv_b,
                        const float* __restrict__ wsu, const float* __restrict__ bsu,
                        const float* __restrict__ wnt, const float* __restrict__ bnt,
                        const float* __restrict__ wtg, const float* __restrict__ btg,
                        const float* __restrict__ wpr, const float* __restrict__ bpr,
                        float* __restrict__ out) {
    extern __shared__ float sm[];
    float* rw = sm;                  // 4096
    float* cb = rw + 4096;           // 64
    float* Wc = cb + 64;             // 64*240
    float* bc = Wc + 64 * 240;       // 240
    float* stage = bc + 240;         // 8 * 128
    int tid = threadIdx.x;
    for (int i = tid; i < 4096; i += 256) rw[i] = root_w[i];
    if (tid < 64) cb[tid] = conv_b[tid];
    for (int i = tid; i < 64 * 16; i += 256)  { int r = i >> 4, c = i & 15;  Wc[r * 240 + c]       = wsu[i]; }
    for (int i = tid; i < 64 * 32; i += 256)  { int r = i >> 5, c = i & 31;  Wc[r * 240 + 16 + c]  = wnt[i]; }
    for (int i = tid; i < 64 * 64; i += 256)  { int r = i >> 6, c = i & 63;  Wc[r * 240 + 48 + c]  = wtg[i]; }
    for (int i = tid; i < 64 * 128; i += 256) { int r = i >> 7, c = i & 127; Wc[r * 240 + 112 + c] = wpr[i]; }
    if (tid < 16)       bc[tid] = bsu[tid];
    else if (tid < 48)  bc[tid] = bnt[tid - 16];
    else if (tid < 112) bc[tid] = btg[tid - 48];
    else if (tid < 240) bc[tid] = bpr[tid - 112];
    __syncthreads();

    int w = tid >> 5, l = tid & 31;
    int n = blockIdx.x * 8 + w;
    if (n >= NN) return;
    float* xs = stage + w * 128;
    float* os = xs + 64;
    xs[l] = g_xf[n * 64 + l];
    xs[l + 32] = g_xf[n * 64 + 32 + l];
    __syncwarp();

    float inv = 1.f / fmaxf(g_cnt[n], 1.f);
#pragma unroll
    for (int half = 0; half < 2; half++) {
        int o = l + 32 * half;
        float acc = cb[o] + g_sums[n * 64 + o] * inv;
#pragma unroll 8
        for (int i = 0; i < 64; i++) acc = fmaf(xs[i], rw[i * 64 + o], acc);
        os[o] = fmaxf(acc, 0.f);
    }
    __syncwarp();

#pragma unroll
    for (int q = 0; q < 8; q++) {
        int t = l + 32 * q;
        if (t < 240) {
            float acc = bc[t];
#pragma unroll 8
            for (int i = 0; i < 64; i++) acc = fmaf(os[i], Wc[i * 240 + t], acc);
            if (t < 16)       out[n * 16 + t] = acc;
            else if (t < 48)  out[240000  + n * 32  + (t - 16)]  = acc;
            else if (t < 112) out[720000  + n * 64  + (t - 48)]  = acc;
            else              out[1680000 + n * 128 + (t - 112)] = acc;
        }
    }
}

// ---------------- launch ----------------
extern "C" void kernel_launch(void* const* d_in, const int* in_sizes, int n_in,
                              void* d_out, int out_size) {
    const float* x        = (const float*)d_in[0];
    const int*   input_np = (const int*)  d_in[1];
    const int*   output_np= (const int*)  d_in[2];
    const int*   edge_idx = (const int*)  d_in[3];
    const int*   edge_nt  = (const int*)  d_in[4];
    const int*   edge_np  = (const int*)  d_in[5];
    const float* edge_sc  = (const float*)d_in[6];
    const float* in_emb   = (const float*)d_in[7];
    const float* out_emb  = (const float*)d_in[8];
    const float* enp_emb  = (const float*)d_in[9];
    const float* ent_emb  = (const float*)d_in[10];
    const float* w1       = (const float*)d_in[11];
    const float* b1       = (const float*)d_in[12];
    const float* w2       = (const float*)d_in[13];
    const float* b2       = (const float*)d_in[14];
    const float* root_w   = (const float*)d_in[15];
    const float* conv_b   = (const float*)d_in[16];
    const float* wsu      = (const float*)d_in[17];
    const float* bsu      = (const float*)d_in[18];
    const float* wnt      = (const float*)d_in[19];
    const float* bnt      = (const float*)d_in[20];
    const float* wtg      = (const float*)d_in[21];
    const float* btg      = (const float*)d_in[22];
    const float* wpr      = (const float*)d_in[23];
    const float* bpr      = (const float*)d_in[24];
    float* out = (float*)d_out;

    const int smem_gemm  = (64 * 132 + 64 * 64) * 4;                       // 50176 B
    const int smem_final = (4096 + 64 + 64 * 240 + 240 + 8 * 128) * 4;     // 83136 B
    cudaFuncSetAttribute(k_gemm,  cudaFuncAttributeMaxDynamicSharedMemorySize, smem_gemm);
    cudaFuncSetAttribute(k_final, cudaFuncAttributeMaxDynamicSharedMemorySize, smem_final);

    k_node_prep<<<(NN + 7) / 8, 256>>>(x, input_np, output_np, in_emb, out_emb);
    k_hist<<<(NE + 255) / 256, 256>>>(edge_idx);
    k_scan<<<1, 1024>>>();
    k_scatter<<<(NE + 255) / 256, 256>>>(edge_idx);
    k_build_M<<<(ND * CT + 255) / 256, 256>>>(w2, b2);
    k_edge_mlp<<<(NE + 7) / 8, 256>>>(edge_nt, edge_np, edge_sc, ent_emb, enp_emb, w1, b1);
    dim3 ggrid(CT / 64, (NN + 127) / 128);
    k_gemm<<<ggrid, 128, smem_gemm>>>();
    k_edge_apply<<<NN, 128>>>(edge_idx);
    k_final<<<(NN + 7) / 8, 256, smem_final>>>(root_w, conv_b,
                                               wsu, bsu, wnt, bnt, wtg, btg, wpr, bpr, out);
}